// round 1
// baseline (speedup 1.0000x reference)
#include <cuda_runtime.h>
#include <math.h>

#define TOK  4096
#define HID  1024
#define IDIM 512
#define NEXP 64
#define TOPK 8
#define CAP  1024

// ---------------- device scratch (no allocation allowed) ----------------
__device__ __align__(16) float g_shared_h [TOK * IDIM];            // 8 MB
__device__ __align__(16) float g_routed_h [NEXP * CAP * IDIM];     // 128 MB
__device__ __align__(16) float g_routed_o [NEXP * CAP * HID];      // 256 MB
__device__ int   g_counts[NEXP];
__device__ int   g_slot_token[NEXP * CAP];
__device__ int   g_topk_slot[TOK * TOPK];
__device__ float g_topk_w  [TOK * TOPK];

__device__ __forceinline__ float silu_f(float v) {
    return v / (1.f + expf(-v));
}

// ---------------- counts reset ----------------
__global__ void zero_counts_kernel() {
    if (threadIdx.x < NEXP) g_counts[threadIdx.x] = 0;
}

// ---------------- gating: scores, top-8, slot assignment ----------------
__global__ void gating_kernel(const float* __restrict__ x,
                              const float* __restrict__ gate_w)
{
    __shared__ __align__(16) float sx[HID];
    __shared__ float sc[NEXP];
    const int t   = blockIdx.x;
    const int tid = threadIdx.x;

    const float* xr = x + (size_t)t * HID;
    for (int i = tid; i < HID / 4; i += 256)
        ((float4*)sx)[i] = ((const float4*)xr)[i];
    __syncthreads();

    const int lane = tid & 31;
    const int w    = tid >> 5;           // 8 warps
    for (int e = w; e < NEXP; e += 8) {
        const float* gw = gate_w + (size_t)e * HID;
        float s = 0.f;
        for (int k = lane; k < HID; k += 32)
            s += sx[k] * __ldg(gw + k);
        #pragma unroll
        for (int o = 16; o > 0; o >>= 1)
            s += __shfl_down_sync(0xffffffffu, s, o);
        if (lane == 0) sc[e] = 1.f / (1.f + expf(-s));
    }
    __syncthreads();

    if (tid == 0) {
        float wv[TOPK]; int se[TOPK]; float wsum = 0.f;
        #pragma unroll
        for (int it = 0; it < TOPK; ++it) {
            float best = -1.f; int bi = 0;
            #pragma unroll
            for (int e = 0; e < NEXP; ++e) {
                float v = sc[e];
                if (v > best) { best = v; bi = e; }
            }
            se[it] = bi; wv[it] = best; wsum += best;
            sc[bi] = -1.f;
        }
        const float inv = 1.f / wsum;
        #pragma unroll
        for (int k = 0; k < TOPK; ++k) {
            int e = se[k];
            float wk = wv[k] * inv;
            int pos = atomicAdd(&g_counts[e], 1);
            int slot;
            if (pos < CAP) { slot = e * CAP + pos; g_slot_token[slot] = t; }
            else           { slot = e * CAP;       wk = 0.f; }   // drop (never hit for this seed)
            g_topk_slot[t * TOPK + k] = slot;
            g_topk_w  [t * TOPK + k] = wk;
        }
    }
}

// ---------------- fused gate+up GEMM with SiLU epilogue ----------------
// C[m,n] = silu(sum_k A[m,k]*Wg[n,k]) * (sum_k A[m,k]*Wu[n,k])
// BM=128, BN=64, BK=16, 256 threads, TM=8 (4+4 split), TN=4
template<bool ROUTED>
__launch_bounds__(256, 2)
__global__ void gemm_dual_silu(const float* __restrict__ X,
                               const float* __restrict__ Wg,
                               const float* __restrict__ Wu)
{
    __shared__ __align__(16) float As [16][132];
    __shared__ __align__(16) float Bgs[16][68];
    __shared__ __align__(16) float Bus[16][68];

    const int e = ROUTED ? blockIdx.z : 0;
    int cnt = TOK;
    if (ROUTED) {
        cnt = g_counts[e]; if (cnt > CAP) cnt = CAP;
        if ((int)(blockIdx.y * 128) >= cnt) return;
        Wg += (size_t)e * IDIM * HID;
        Wu += (size_t)e * IDIM * HID;
    }
    const int m0 = blockIdx.y * 128;
    const int n0 = blockIdx.x * 64;
    const int tid = threadIdx.x;
    const int tx = tid & 15, ty = tid >> 4;

    // A loader: 128x16 tile, thread loads 2 float4 (rows ar, ar+64)
    const int ar = tid >> 2;
    const int ac = (tid & 3) << 2;
    const int r0 = m0 + ar, r1 = r0 + 64;
    bool av0, av1;
    const float* Arow0 = nullptr;
    const float* Arow1 = nullptr;
    if (ROUTED) {
        av0 = r0 < cnt; av1 = r1 < cnt;
        if (av0) Arow0 = X + (size_t)g_slot_token[e * CAP + r0] * HID;
        if (av1) Arow1 = X + (size_t)g_slot_token[e * CAP + r1] * HID;
    } else {
        av0 = true; av1 = true;
        Arow0 = X + (size_t)r0 * HID;
        Arow1 = X + (size_t)r1 * HID;
    }
    // B loader: 64x16 tile, 1 float4 per thread
    const float* Bgrow = Wg + (size_t)(n0 + ar) * HID;
    const float* Burow = Wu + (size_t)(n0 + ar) * HID;

    float ag[8][4], au[8][4];
    #pragma unroll
    for (int i = 0; i < 8; ++i)
        #pragma unroll
        for (int j = 0; j < 4; ++j) { ag[i][j] = 0.f; au[i][j] = 0.f; }

    for (int k0 = 0; k0 < HID; k0 += 16) {
        float4 a0 = av0 ? *(const float4*)(Arow0 + k0 + ac) : make_float4(0,0,0,0);
        float4 a1 = av1 ? *(const float4*)(Arow1 + k0 + ac) : make_float4(0,0,0,0);
        float4 bg = *(const float4*)(Bgrow + k0 + ac);
        float4 bu = *(const float4*)(Burow + k0 + ac);

        As[ac+0][ar]    = a0.x; As[ac+1][ar]    = a0.y; As[ac+2][ar]    = a0.z; As[ac+3][ar]    = a0.w;
        As[ac+0][ar+64] = a1.x; As[ac+1][ar+64] = a1.y; As[ac+2][ar+64] = a1.z; As[ac+3][ar+64] = a1.w;
        Bgs[ac+0][ar] = bg.x; Bgs[ac+1][ar] = bg.y; Bgs[ac+2][ar] = bg.z; Bgs[ac+3][ar] = bg.w;
        Bus[ac+0][ar] = bu.x; Bus[ac+1][ar] = bu.y; Bus[ac+2][ar] = bu.z; Bus[ac+3][ar] = bu.w;
        __syncthreads();

        #pragma unroll
        for (int k = 0; k < 16; ++k) {
            float4 x0 = *(const float4*)&As[k][ty * 4];
            float4 x1 = *(const float4*)&As[k][64 + ty * 4];
            float4 g4 = *(const float4*)&Bgs[k][tx * 4];
            float4 u4 = *(const float4*)&Bus[k][tx * 4];
            float avv[8] = {x0.x, x0.y, x0.z, x0.w, x1.x, x1.y, x1.z, x1.w};
            float gvv[4] = {g4.x, g4.y, g4.z, g4.w};
            float uvv[4] = {u4.x, u4.y, u4.z, u4.w};
            #pragma unroll
            for (int i = 0; i < 8; ++i)
                #pragma unroll
                for (int j = 0; j < 4; ++j) {
                    ag[i][j] = fmaf(avv[i], gvv[j], ag[i][j]);
                    au[i][j] = fmaf(avv[i], uvv[j], au[i][j]);
                }
        }
        __syncthreads();
    }

    float* Out = ROUTED ? g_routed_h : g_shared_h;
    #pragma unroll
    for (int i = 0; i < 8; ++i) {
        const int m = m0 + ((i < 4) ? (ty * 4 + i) : (64 + ty * 4 + i - 4));
        if (ROUTED && m >= cnt) continue;
        const size_t row = ROUTED ? (size_t)(e * CAP + m) : (size_t)m;
        float4 o;
        o.x = silu_f(ag[i][0]) * au[i][0];
        o.y = silu_f(ag[i][1]) * au[i][1];
        o.z = silu_f(ag[i][2]) * au[i][2];
        o.w = silu_f(ag[i][3]) * au[i][3];
        *(float4*)(Out + row * IDIM + n0 + tx * 4) = o;
    }
}

// ---------------- down-projection GEMM ----------------
// C[m,n] = sum_k A[m,k]*Wd[n,k]; A is [*, IDIM], Wd is [HID, IDIM]
// BM=128, BN=128, BK=8, 256 threads, TM=8/TN=8 split 4+4
template<bool ROUTED>
__launch_bounds__(256, 2)
__global__ void gemm_down(const float* __restrict__ Wd,
                          float* __restrict__ OutShared)
{
    __shared__ __align__(16) float As[8][132];
    __shared__ __align__(16) float Bs[8][132];

    const int e = ROUTED ? blockIdx.z : 0;
    int cnt = TOK;
    const float* Abase = ROUTED ? g_routed_h : g_shared_h;
    if (ROUTED) {
        cnt = g_counts[e]; if (cnt > CAP) cnt = CAP;
        if ((int)(blockIdx.y * 128) >= cnt) return;
        Wd += (size_t)e * HID * IDIM;
    }
    const int m0 = blockIdx.y * 128;
    const int n0 = blockIdx.x * 128;
    const int tid = threadIdx.x;
    const int tx = tid & 15, ty = tid >> 4;

    const int ar = tid >> 1;            // 0..127
    const int ac = (tid & 1) << 2;      // 0 or 4
    const int rowm = m0 + ar;
    const bool av = (!ROUTED) || (rowm < cnt);
    const size_t arow = ROUTED ? (size_t)(e * CAP + rowm) : (size_t)rowm;
    const float* Arow = Abase + arow * IDIM;
    const float* Brow = Wd + (size_t)(n0 + ar) * IDIM;

    float acc[8][8];
    #pragma unroll
    for (int i = 0; i < 8; ++i)
        #pragma unroll
        for (int j = 0; j < 8; ++j) acc[i][j] = 0.f;

    for (int k0 = 0; k0 < IDIM; k0 += 8) {
        float4 a = av ? *(const float4*)(Arow + k0 + ac) : make_float4(0,0,0,0);
        float4 b = *(const float4*)(Brow + k0 + ac);
        As[ac+0][ar] = a.x; As[ac+1][ar] = a.y; As[ac+2][ar] = a.z; As[ac+3][ar] = a.w;
        Bs[ac+0][ar] = b.x; Bs[ac+1][ar] = b.y; Bs[ac+2][ar] = b.z; Bs[ac+3][ar] = b.w;
        __syncthreads();

        #pragma unroll
        for (int k = 0; k < 8; ++k) {
            float4 x0 = *(const float4*)&As[k][ty * 4];
            float4 x1 = *(const float4*)&As[k][64 + ty * 4];
            float4 b0 = *(const float4*)&Bs[k][tx * 4];
            float4 b1 = *(const float4*)&Bs[k][64 + tx * 4];
            float avv[8] = {x0.x, x0.y, x0.z, x0.w, x1.x, x1.y, x1.z, x1.w};
            float bvv[8] = {b0.x, b0.y, b0.z, b0.w, b1.x, b1.y, b1.z, b1.w};
            #pragma unroll
            for (int i = 0; i < 8; ++i)
                #pragma unroll
                for (int j = 0; j < 8; ++j)
                    acc[i][j] = fmaf(avv[i], bvv[j], acc[i][j]);
        }
        __syncthreads();
    }

    float* Out = ROUTED ? g_routed_o : OutShared;
    #pragma unroll
    for (int i = 0; i < 8; ++i) {
        const int m = m0 + ((i < 4) ? (ty * 4 + i) : (64 + ty * 4 + i - 4));
        if (ROUTED && m >= cnt) continue;
        const size_t row = ROUTED ? (size_t)(e * CAP + m) : (size_t)m;
        float4 o0, o1;
        o0.x = acc[i][0]; o0.y = acc[i][1]; o0.z = acc[i][2]; o0.w = acc[i][3];
        o1.x = acc[i][4]; o1.y = acc[i][5]; o1.z = acc[i][6]; o1.w = acc[i][7];
        *(float4*)(Out + row * HID + n0 + tx * 4)      = o0;
        *(float4*)(Out + row * HID + n0 + 64 + tx * 4) = o1;
    }
}

// ---------------- combine: out = shared + sum_k w_k * routed_row_k ----------------
__global__ void combine_kernel(float* __restrict__ out)
{
    const int idx = blockIdx.x * blockDim.x + threadIdx.x;   // over TOK*HID/4
    const int t = idx >> 8;          // HID/4 = 256 float4 per row
    const int c = idx & 255;
    float4 acc = ((float4*)out)[idx];
    const float4* ro = (const float4*)g_routed_o;
    #pragma unroll
    for (int k = 0; k < TOPK; ++k) {
        const int   slot = g_topk_slot[t * TOPK + k];
        const float wk   = g_topk_w  [t * TOPK + k];
        float4 v = ro[(size_t)slot * 256 + c];
        acc.x = fmaf(wk, v.x, acc.x);
        acc.y = fmaf(wk, v.y, acc.y);
        acc.z = fmaf(wk, v.z, acc.z);
        acc.w = fmaf(wk, v.w, acc.w);
    }
    ((float4*)out)[idx] = acc;
}

// ---------------- launch ----------------
extern "C" void kernel_launch(void* const* d_in, const int* in_sizes, int n_in,
                              void* d_out, int out_size)
{
    const float* x   = (const float*)d_in[0];
    const float* gw  = (const float*)d_in[1];
    const float* swg = (const float*)d_in[2];
    const float* swu = (const float*)d_in[3];
    const float* swd = (const float*)d_in[4];
    const float* ewg = (const float*)d_in[5];
    const float* ewu = (const float*)d_in[6];
    const float* ewd = (const float*)d_in[7];
    float* out = (float*)d_out;

    zero_counts_kernel<<<1, 64>>>();
    gating_kernel<<<TOK, 256>>>(x, gw);

    // shared expert
    gemm_dual_silu<false><<<dim3(IDIM / 64, TOK / 128), 256>>>(x, swg, swu);
    gemm_down<false><<<dim3(HID / 128, TOK / 128), 256>>>(swd, out);

    // routed experts
    gemm_dual_silu<true><<<dim3(IDIM / 64, CAP / 128, NEXP), 256>>>(x, ewg, ewu);
    gemm_down<true><<<dim3(HID / 128, CAP / 128, NEXP), 256>>>(ewd, out);

    combine_kernel<<<(TOK * HID / 4) / 256, 256>>>(out);
}

// round 7
// speedup vs baseline: 1.2483x; 1.2483x over previous
#include <cuda_runtime.h>
#include <cuda_bf16.h>
#include <math.h>
#include <stdint.h>

#define TOK  4096
#define HID  1024
#define IDIM 512
#define NEXP 64
#define TOPK 8
#define CAP  1024

// ---------------- device scratch (~392MB, same scale as passing R1) ----------------
__device__ __align__(16) float g_Hs[TOK * IDIM];            // 8 MB
__device__ __align__(16) float g_Hr[NEXP * CAP * IDIM];     // 128 MB
__device__ __align__(16) float g_routed_o[NEXP * CAP * HID];// 256 MB
__device__ int   g_counts[NEXP];
__device__ int   g_slot_token[NEXP * CAP];
__device__ int   g_topk_slot[TOK * TOPK];
__device__ float g_topk_w  [TOK * TOPK];

// ---------------- helpers ----------------
__device__ __forceinline__ uint32_t smem_u32(const void* p) {
    uint32_t a;
    asm("{ .reg .u64 t; cvta.to.shared.u64 t, %1; cvt.u32.u64 %0, t; }" : "=r"(a) : "l"(p));
    return a;
}
__device__ __forceinline__ void cpa16(uint32_t d, const void* s) {
    asm volatile("cp.async.cg.shared.global [%0], [%1], 16;" :: "r"(d), "l"(s));
}
#define CP_COMMIT() asm volatile("cp.async.commit_group;" ::: "memory")
#define CP_WAIT1()  asm volatile("cp.async.wait_group 1;" ::: "memory")
#define CP_WAIT0()  asm volatile("cp.async.wait_group 0;" ::: "memory")

#define LDSM4V(R0, R1, R2, R3, ADDR) \
    asm volatile("ldmatrix.sync.aligned.m8n8.x4.shared.b16 {%0,%1,%2,%3}, [%4];" \
        : "=r"(R0), "=r"(R1), "=r"(R2), "=r"(R3) : "r"(ADDR));

#define DECL4(N) float N##_x = 0.f, N##_y = 0.f, N##_z = 0.f, N##_w = 0.f

#define MMA4(C, A0, A1, A2, A3, B0, B1) \
    asm volatile("mma.sync.aligned.m16n8k16.row.col.f32.bf16.bf16.f32 " \
        "{%0,%1,%2,%3}, {%4,%5,%6,%7}, {%8,%9}, {%0,%1,%2,%3};" \
        : "+f"(C##_x), "+f"(C##_y), "+f"(C##_z), "+f"(C##_w) \
        : "r"(A0), "r"(A1), "r"(A2), "r"(A3), "r"(B0), "r"(B1));

// 6 MMAs: (Ah*Bh + Al*Bh + Ah*Bl) into CA (n8 pair 0) and CB (n8 pair 1)
#define TRIP(CA, CB, A0, A1, A2, A3, L0, L1, L2, L3) \
    MMA4(CA, A0, A1, A2, A3, th0, th1) MMA4(CB, A0, A1, A2, A3, th2, th3) \
    MMA4(CA, L0, L1, L2, L3, th0, th1) MMA4(CB, L0, L1, L2, L3, th2, th3) \
    MMA4(CA, A0, A1, A2, A3, tl0, tl1) MMA4(CB, A0, A1, A2, A3, tl2, tl3)

__device__ __forceinline__ float silu_f(float v) { return v / (1.f + expf(-v)); }

// bf16 round-to-nearest-even via integer bit math (no address-of anywhere)
__device__ __forceinline__ void split1(float v, uint32_t& h, uint32_t& l) {
    uint32_t b = __float_as_uint(v);
    uint32_t hb = (b + 0x7FFFu + ((b >> 16) & 1u)) >> 16;
    float hf = __uint_as_float(hb << 16);
    float lv = v - hf;
    uint32_t b2 = __float_as_uint(lv);
    uint32_t lb = (b2 + 0x7FFFu + ((b2 >> 16) & 1u)) >> 16;
    h = hb; l = lb;
}
__device__ __forceinline__ void split4(float4 v, uint32_t& h01, uint32_t& h23,
                                       uint32_t& l01, uint32_t& l23) {
    uint32_t h0,h1,h2,h3,l0,l1,l2,l3;
    split1(v.x,h0,l0); split1(v.y,h1,l1); split1(v.z,h2,l2); split1(v.w,h3,l3);
    h01 = h0 | (h1 << 16); h23 = h2 | (h3 << 16);
    l01 = l0 | (l1 << 16); l23 = l2 | (l3 << 16);
}
// one unit = 16 fp32 (64B) -> 16 bf16 hi (32B) + 16 bf16 lo (32B)
__device__ __forceinline__ void convert_unit(const char* fsrc, char* hdst, char* ldst) {
    float4 v0 = *(const float4*)(fsrc);
    float4 v1 = *(const float4*)(fsrc + 16);
    float4 v2 = *(const float4*)(fsrc + 32);
    float4 v3 = *(const float4*)(fsrc + 48);
    uint32_t a,b,la,lb, c,d,lc,ld;
    split4(v0, a,b,la,lb); split4(v1, c,d,lc,ld);
    *(uint4*)(hdst)      = make_uint4(a,b,c,d);
    *(uint4*)(ldst)      = make_uint4(la,lb,lc,ld);
    split4(v2, a,b,la,lb); split4(v3, c,d,lc,ld);
    *(uint4*)(hdst + 16) = make_uint4(a,b,c,d);
    *(uint4*)(ldst + 16) = make_uint4(la,lb,lc,ld);
}

// ---------------- small kernels (identical to passing R1) ----------------
__global__ void zero_counts_kernel() {
    if (threadIdx.x < NEXP) g_counts[threadIdx.x] = 0;
}

__global__ void gating_kernel(const float* __restrict__ x,
                              const float* __restrict__ gate_w)
{
    __shared__ __align__(16) float sx[HID];
    __shared__ float sc[NEXP];
    const int t = blockIdx.x, tid = threadIdx.x;
    const float* xr = x + (size_t)t * HID;
    for (int i = tid; i < HID / 4; i += 256)
        ((float4*)sx)[i] = ((const float4*)xr)[i];
    __syncthreads();
    const int lane = tid & 31, w = tid >> 5;
    for (int e = w; e < NEXP; e += 8) {
        const float* gw = gate_w + (size_t)e * HID;
        float s = 0.f;
        for (int k = lane; k < HID; k += 32) s += sx[k] * __ldg(gw + k);
        #pragma unroll
        for (int o = 16; o > 0; o >>= 1) s += __shfl_down_sync(0xffffffffu, s, o);
        if (lane == 0) sc[e] = 1.f / (1.f + expf(-s));
    }
    __syncthreads();
    if (tid == 0) {
        float wv[TOPK]; int se[TOPK]; float wsum = 0.f;
        #pragma unroll
        for (int it = 0; it < TOPK; ++it) {
            float best = -1.f; int bi = 0;
            #pragma unroll
            for (int e = 0; e < NEXP; ++e) { float v = sc[e]; if (v > best) { best = v; bi = e; } }
            se[it] = bi; wv[it] = best; wsum += best; sc[bi] = -1.f;
        }
        const float inv = 1.f / wsum;
        #pragma unroll
        for (int k = 0; k < TOPK; ++k) {
            int e = se[k];
            float wk = wv[k] * inv;
            int pos = atomicAdd(&g_counts[e], 1);
            int slot;
            if (pos < CAP) { slot = e * CAP + pos; g_slot_token[slot] = t; }
            else           { slot = e * CAP;       wk = 0.f; }
            g_topk_slot[t * TOPK + k] = slot;
            g_topk_w  [t * TOPK + k] = wk;
        }
    }
}

// ======================================================================
// smem maps (bytes from dynamic smem base), fp32 staging stride 144B/row,
// bf16 operand stride 80B/row (ldmatrix conflict-free; verified R6 math).
// GU:   fp32 stage: A 0..18432, Wg 18432..27648, Wu 27648..36864 (x2 stages)
//       bf16: Ah 73728, Al 83968, Gh 94208, Gl 99328, Uh 104448, Ul 109568
// DOWN: fp32 stage: A 0..18432, W 18432..36864 (x2 stages)
//       bf16: Ah 73728, Al 83968, Wh 94208, Wl 104448
// ======================================================================
#define STG    36864u
#define OFF_BA 73728u
#define GU_SMEM 114688
#define DN_SMEM 114688

// ---------------- fused gate+up GEMM (bf16x3 HMMA, on-the-fly split) ----------------
// BM=128 BN=64 BK=32, 8 warps (4Mx2N), warp tile 32x32 per matrix (G and U)
template<bool ROUTED>
__global__ void __launch_bounds__(256) hmma_gu(const float* __restrict__ X,
                                               const float* __restrict__ Wg,
                                               const float* __restrict__ Wu)
{
    extern __shared__ __align__(16) char sm[];
    const uint32_t sb = smem_u32(sm);

    int e = 0, cnt = TOK;
    if (ROUTED) {
        e = blockIdx.z;
        cnt = g_counts[e]; if (cnt > CAP) cnt = CAP;
        if ((int)(blockIdx.y * 128) >= cnt) return;
        Wg += (size_t)e * IDIM * HID;
        Wu += (size_t)e * IDIM * HID;
    }
    const int m0 = blockIdx.y * 128, n0 = blockIdx.x * 64;
    const int tid = threadIdx.x, lane = tid & 31, wid = tid >> 5;

    // unit mapping: every thread owns one A unit (16 fp32) and one W unit
    const int urow = tid >> 1, ugrp = tid & 1;                 // A row, col group
    int tok = ROUTED ? ((m0 + urow < cnt) ? g_slot_token[e * CAP + m0 + urow] : 0) : (m0 + urow);
    const float* pA = X + (size_t)tok * HID + ugrp * 16;
    const int wunit = tid & 127;
    const int wrow = wunit >> 1, wgrp = wunit & 1;
    const bool isWu = tid >= 128;
    const float* pW = (isWu ? Wu : Wg) + (size_t)(n0 + wrow) * HID + wgrp * 16;
    const uint32_t fAoff = (uint32_t)urow * 144u + (uint32_t)ugrp * 64u;
    const uint32_t fWoff = (isWu ? 27648u : 18432u) + (uint32_t)wrow * 144u + (uint32_t)wgrp * 64u;
    const uint32_t bWhi = isWu ? 104448u : 94208u;
    const uint32_t bWlo = isWu ? 109568u : 99328u;

    const int m_base = (wid >> 1) * 32, n_base = (wid & 1) * 32;
    const uint32_t aOff = (uint32_t)((m_base + (lane & 15)) * 40 + (lane >> 4) * 8) * 2u;
    const uint32_t bOff = (uint32_t)((n_base + ((lane >> 4) & 1) * 8 + (lane & 7)) * 40
                                     + ((lane >> 3) & 1) * 8) * 2u;
    const uint32_t bAh = sb + OFF_BA, bAl = sb + 83968u;
    const uint32_t bGh = sb + 94208u, bGl = sb + 99328u;
    const uint32_t bUh = sb + 104448u, bUl = sb + 109568u;

    DECL4(cg00); DECL4(cg01); DECL4(cg02); DECL4(cg03);
    DECL4(cg10); DECL4(cg11); DECL4(cg12); DECL4(cg13);
    DECL4(cu00); DECL4(cu01); DECL4(cu02); DECL4(cu03);
    DECL4(cu10); DECL4(cu11); DECL4(cu12); DECL4(cu13);

#define GU_LOAD(KT_) { \
    const uint32_t s_ = (uint32_t)((KT_) & 1) * STG; \
    const int k0_ = (KT_) * 32; \
    uint32_t ad_ = sb + s_ + fAoff; \
    cpa16(ad_,      pA + k0_);      cpa16(ad_ + 16, pA + k0_ + 4); \
    cpa16(ad_ + 32, pA + k0_ + 8);  cpa16(ad_ + 48, pA + k0_ + 12); \
    uint32_t wd_ = sb + s_ + fWoff; \
    cpa16(wd_,      pW + k0_);      cpa16(wd_ + 16, pW + k0_ + 4); \
    cpa16(wd_ + 32, pW + k0_ + 8);  cpa16(wd_ + 48, pW + k0_ + 12); \
    CP_COMMIT(); }

    GU_LOAD(0) GU_LOAD(1)

    const int KT = HID / 32;   // 32
    for (int kt = 0; kt < KT; ++kt) {
        if (kt + 1 < KT) { CP_WAIT1(); } else { CP_WAIT0(); }
        __syncthreads();
        {
            const uint32_t s = (uint32_t)(kt & 1) * STG;
            convert_unit(sm + s + fAoff, sm + OFF_BA + urow * 80 + ugrp * 32,
                                         sm + 83968 + urow * 80 + ugrp * 32);
            convert_unit(sm + s + fWoff, sm + bWhi + wrow * 80 + wgrp * 32,
                                         sm + bWlo + wrow * 80 + wgrp * 32);
        }
        __syncthreads();
        if (kt + 2 < KT) GU_LOAD(kt + 2)
        #pragma unroll
        for (int kk = 0; kk < 2; ++kk) {
            const uint32_t kka = aOff + kk * 32u;
            const uint32_t kkb = bOff + kk * 32u;
            uint32_t a00,a01,a02,a03, a10,a11,a12,a13;
            uint32_t l00,l01,l02,l03, l10,l11,l12,l13;
            LDSM4V(a00,a01,a02,a03, bAh + kka)
            LDSM4V(a10,a11,a12,a13, bAh + kka + 1280u)
            LDSM4V(l00,l01,l02,l03, bAl + kka)
            LDSM4V(l10,l11,l12,l13, bAl + kka + 1280u)
            uint32_t th0,th1,th2,th3, tl0,tl1,tl2,tl3;
            // p=0 gate
            LDSM4V(th0,th1,th2,th3, bGh + kkb)
            LDSM4V(tl0,tl1,tl2,tl3, bGl + kkb)
            TRIP(cg00, cg01, a00,a01,a02,a03, l00,l01,l02,l03)
            TRIP(cg10, cg11, a10,a11,a12,a13, l10,l11,l12,l13)
            // p=0 up
            LDSM4V(th0,th1,th2,th3, bUh + kkb)
            LDSM4V(tl0,tl1,tl2,tl3, bUl + kkb)
            TRIP(cu00, cu01, a00,a01,a02,a03, l00,l01,l02,l03)
            TRIP(cu10, cu11, a10,a11,a12,a13, l10,l11,l12,l13)
            // p=1 gate
            LDSM4V(th0,th1,th2,th3, bGh + kkb + 1280u)
            LDSM4V(tl0,tl1,tl2,tl3, bGl + kkb + 1280u)
            TRIP(cg02, cg03, a00,a01,a02,a03, l00,l01,l02,l03)
            TRIP(cg12, cg13, a10,a11,a12,a13, l10,l11,l12,l13)
            // p=1 up
            LDSM4V(th0,th1,th2,th3, bUh + kkb + 1280u)
            LDSM4V(tl0,tl1,tl2,tl3, bUl + kkb + 1280u)
            TRIP(cu02, cu03, a00,a01,a02,a03, l00,l01,l02,l03)
            TRIP(cu12, cu13, a10,a11,a12,a13, l10,l11,l12,l13)
        }
        __syncthreads();
    }
#undef GU_LOAD

    float* H = ROUTED ? g_Hr : g_Hs;
    const int er = lane >> 2, ec = (lane & 3) * 2;
#define GU_EPI(CG, CU, MT, NT) { \
    const int col = n0 + n_base + (NT) * 8 + ec; \
    { const int mloc = m_base + (MT) * 16 + er; \
      if (!(ROUTED && (m0 + mloc) >= cnt)) { \
        float2 v = make_float2(silu_f(CG##_x) * CU##_x, silu_f(CG##_y) * CU##_y); \
        *(float2*)(H + ((ROUTED ? (size_t)e * CAP : 0) + m0 + mloc) * IDIM + col) = v; } } \
    { const int mloc = m_base + (MT) * 16 + er + 8; \
      if (!(ROUTED && (m0 + mloc) >= cnt)) { \
        float2 v = make_float2(silu_f(CG##_z) * CU##_z, silu_f(CG##_w) * CU##_w); \
        *(float2*)(H + ((ROUTED ? (size_t)e * CAP : 0) + m0 + mloc) * IDIM + col) = v; } } }
    GU_EPI(cg00, cu00, 0, 0) GU_EPI(cg01, cu01, 0, 1)
    GU_EPI(cg02, cu02, 0, 2) GU_EPI(cg03, cu03, 0, 3)
    GU_EPI(cg10, cu10, 1, 0) GU_EPI(cg11, cu11, 1, 1)
    GU_EPI(cg12, cu12, 1, 2) GU_EPI(cg13, cu13, 1, 3)
#undef GU_EPI
}

// ---------------- down GEMM (bf16x3 HMMA, on-the-fly split) ----------------
// BM=128 BN=128 BK=32, 8 warps (4Mx2N), warp tile 32x64
template<bool ROUTED>
__global__ void __launch_bounds__(256) hmma_down(const float* __restrict__ Wd,
                                                 float* __restrict__ out)
{
    extern __shared__ __align__(16) char sm[];
    const uint32_t sb = smem_u32(sm);

    int e = 0, cnt = TOK;
    if (ROUTED) {
        e = blockIdx.z;
        cnt = g_counts[e]; if (cnt > CAP) cnt = CAP;
        if ((int)(blockIdx.y * 128) >= cnt) return;
        Wd += (size_t)e * HID * IDIM;
    }
    const int m0 = blockIdx.y * 128, n0 = blockIdx.x * 128;
    const int tid = threadIdx.x, lane = tid & 31, wid = tid >> 5;

    const int urow = tid >> 1, ugrp = tid & 1;
    const float* Hbase = ROUTED ? g_Hr : g_Hs;
    const float* pA = Hbase + ((ROUTED ? (size_t)e * CAP : 0) + m0 + urow) * IDIM + ugrp * 16;
    const float* pW = Wd + (size_t)(n0 + urow) * IDIM + ugrp * 16;
    const uint32_t fAoff = (uint32_t)urow * 144u + (uint32_t)ugrp * 64u;
    const uint32_t fWoff = 18432u + fAoff;

    const int m_base = (wid >> 1) * 32, n_base = (wid & 1) * 64;
    const uint32_t aOff = (uint32_t)((m_base + (lane & 15)) * 40 + (lane >> 4) * 8) * 2u;
    const uint32_t bOff = (uint32_t)((n_base + ((lane >> 4) & 1) * 8 + (lane & 7)) * 40
                                     + ((lane >> 3) & 1) * 8) * 2u;
    const uint32_t bAh = sb + OFF_BA, bAl = sb + 83968u;
    const uint32_t bWh = sb + 94208u, bWl = sb + 104448u;

    DECL4(d00); DECL4(d01); DECL4(d02); DECL4(d03);
    DECL4(d04); DECL4(d05); DECL4(d06); DECL4(d07);
    DECL4(d10); DECL4(d11); DECL4(d12); DECL4(d13);
    DECL4(d14); DECL4(d15); DECL4(d16); DECL4(d17);

#define DN_LOAD(KT_) { \
    const uint32_t s_ = (uint32_t)((KT_) & 1) * STG; \
    const int k0_ = (KT_) * 32; \
    uint32_t ad_ = sb + s_ + fAoff; \
    cpa16(ad_,      pA + k0_);      cpa16(ad_ + 16, pA + k0_ + 4); \
    cpa16(ad_ + 32, pA + k0_ + 8);  cpa16(ad_ + 48, pA + k0_ + 12); \
    uint32_t wd_ = sb + s_ + fWoff; \
    cpa16(wd_,      pW + k0_);      cpa16(wd_ + 16, pW + k0_ + 4); \
    cpa16(wd_ + 32, pW + k0_ + 8);  cpa16(wd_ + 48, pW + k0_ + 12); \
    CP_COMMIT(); }

    DN_LOAD(0) DN_LOAD(1)

    const int KT = IDIM / 32;   // 16
    for (int kt = 0; kt < KT; ++kt) {
        if (kt + 1 < KT) { CP_WAIT1(); } else { CP_WAIT0(); }
        __syncthreads();
        {
            const uint32_t s = (uint32_t)(kt & 1) * STG;
            convert_unit(sm + s + fAoff, sm + OFF_BA + urow * 80 + ugrp * 32,
                                         sm + 83968 + urow * 80 + ugrp * 32);
            convert_unit(sm + s + fWoff, sm + 94208 + urow * 80 + ugrp * 32,
                                         sm + 104448 + urow * 80 + ugrp * 32);
        }
        __syncthreads();
        if (kt + 2 < KT) DN_LOAD(kt + 2)
        #pragma unroll
        for (int kk = 0; kk < 2; ++kk) {
            const uint32_t kka = aOff + kk * 32u;
            const uint32_t kkb = bOff + kk * 32u;
            uint32_t a00,a01,a02,a03, a10,a11,a12,a13;
            uint32_t l00,l01,l02,l03, l10,l11,l12,l13;
            LDSM4V(a00,a01,a02,a03, bAh + kka)
            LDSM4V(a10,a11,a12,a13, bAh + kka + 1280u)
            LDSM4V(l00,l01,l02,l03, bAl + kka)
            LDSM4V(l10,l11,l12,l13, bAl + kka + 1280u)
            uint32_t th0,th1,th2,th3, tl0,tl1,tl2,tl3;
            // p=0
            LDSM4V(th0,th1,th2,th3, bWh + kkb)
            LDSM4V(tl0,tl1,tl2,tl3, bWl + kkb)
            TRIP(d00, d01, a00,a01,a02,a03, l00,l01,l02,l03)
            TRIP(d10, d11, a10,a11,a12,a13, l10,l11,l12,l13)
            // p=1
            LDSM4V(th0,th1,th2,th3, bWh + kkb + 1280u)
            LDSM4V(tl0,tl1,tl2,tl3, bWl + kkb + 1280u)
            TRIP(d02, d03, a00,a01,a02,a03, l00,l01,l02,l03)
            TRIP(d12, d13, a10,a11,a12,a13, l10,l11,l12,l13)
            // p=2
            LDSM4V(th0,th1,th2,th3, bWh + kkb + 2560u)
            LDSM4V(tl0,tl1,tl2,tl3, bWl + kkb + 2560u)
            TRIP(d04, d05, a00,a01,a02,a03, l00,l01,l02,l03)
            TRIP(d14, d15, a10,a11,a12,a13, l10,l11,l12,l13)
            // p=3
            LDSM4V(th0,th1,th2,th3, bWh + kkb + 3840u)
            LDSM4V(tl0,tl1,tl2,tl3, bWl + kkb + 3840u)
            TRIP(d06, d07, a00,a01,a02,a03, l00,l01,l02,l03)
            TRIP(d16, d17, a10,a11,a12,a13, l10,l11,l12,l13)
        }
        __syncthreads();
    }
#undef DN_LOAD

    const int er = lane >> 2, ec = (lane & 3) * 2;
#define DN_EPI(C, MT, NT) { \
    const int col = n0 + n_base + (NT) * 8 + ec; \
    { const int mloc = m_base + (MT) * 16 + er; \
      if (!(ROUTED && (m0 + mloc) >= cnt)) { \
        float2 v = make_float2(C##_x, C##_y); \
        if (ROUTED) *(float2*)(g_routed_o + ((size_t)e * CAP + m0 + mloc) * HID + col) = v; \
        else        *(float2*)(out + (size_t)(m0 + mloc) * HID + col) = v; } } \
    { const int mloc = m_base + (MT) * 16 + er + 8; \
      if (!(ROUTED && (m0 + mloc) >= cnt)) { \
        float2 v = make_float2(C##_z, C##_w); \
        if (ROUTED) *(float2*)(g_routed_o + ((size_t)e * CAP + m0 + mloc) * HID + col) = v; \
        else        *(float2*)(out + (size_t)(m0 + mloc) * HID + col) = v; } } }
    DN_EPI(d00, 0, 0) DN_EPI(d01, 0, 1) DN_EPI(d02, 0, 2) DN_EPI(d03, 0, 3)
    DN_EPI(d04, 0, 4) DN_EPI(d05, 0, 5) DN_EPI(d06, 0, 6) DN_EPI(d07, 0, 7)
    DN_EPI(d10, 1, 0) DN_EPI(d11, 1, 1) DN_EPI(d12, 1, 2) DN_EPI(d13, 1, 3)
    DN_EPI(d14, 1, 4) DN_EPI(d15, 1, 5) DN_EPI(d16, 1, 6) DN_EPI(d17, 1, 7)
#undef DN_EPI
}

// ---------------- combine ----------------
__global__ void combine_kernel(float* __restrict__ out)
{
    const int idx = blockIdx.x * blockDim.x + threadIdx.x;
    const int t = idx >> 8;
    const int c = idx & 255;
    float4 acc = ((float4*)out)[idx];
    const float4* ro = (const float4*)g_routed_o;
    #pragma unroll
    for (int k = 0; k < TOPK; ++k) {
        const int   slot = g_topk_slot[t * TOPK + k];
        const float wk   = g_topk_w  [t * TOPK + k];
        float4 v = ro[(size_t)slot * 256 + c];
        acc.x = fmaf(wk, v.x, acc.x);
        acc.y = fmaf(wk, v.y, acc.y);
        acc.z = fmaf(wk, v.z, acc.z);
        acc.w = fmaf(wk, v.w, acc.w);
    }
    ((float4*)out)[idx] = acc;
}

// ---------------- launch ----------------
extern "C" void kernel_launch(void* const* d_in, const int* in_sizes, int n_in,
                              void* d_out, int out_size)
{
    const float* x   = (const float*)d_in[0];
    const float* gw  = (const float*)d_in[1];
    const float* swg = (const float*)d_in[2];
    const float* swu = (const float*)d_in[3];
    const float* swd = (const float*)d_in[4];
    const float* ewg = (const float*)d_in[5];
    const float* ewu = (const float*)d_in[6];
    const float* ewd = (const float*)d_in[7];
    float* out = (float*)d_out;

    cudaFuncSetAttribute(hmma_gu<false>,   cudaFuncAttributeMaxDynamicSharedMemorySize, GU_SMEM);
    cudaFuncSetAttribute(hmma_gu<true>,    cudaFuncAttributeMaxDynamicSharedMemorySize, GU_SMEM);
    cudaFuncSetAttribute(hmma_down<false>, cudaFuncAttributeMaxDynamicSharedMemorySize, DN_SMEM);
    cudaFuncSetAttribute(hmma_down<true>,  cudaFuncAttributeMaxDynamicSharedMemorySize, DN_SMEM);

    zero_counts_kernel<<<1, 64>>>();
    gating_kernel<<<TOK, 256>>>(x, gw);

    // shared expert
    hmma_gu<false><<<dim3(IDIM/64, TOK/128), 256, GU_SMEM>>>(x, swg, swu);
    hmma_down<false><<<dim3(HID/128, TOK/128), 256, DN_SMEM>>>(swd, out);

    // routed experts
    hmma_gu<true><<<dim3(IDIM/64, CAP/128, NEXP), 256, GU_SMEM>>>(x, ewg, ewu);
    hmma_down<true><<<dim3(HID/128, CAP/128, NEXP), 256, DN_SMEM>>>(ewd, out);

    combine_kernel<<<(TOK*HID/4) / 256, 256>>>(out);
}